// round 15
// baseline (speedup 1.0000x reference)
#include <cuda_runtime.h>
#include <cstdint>

#define B_  8
#define C_  128
#define H_  192
#define W_  448
#define ND  49

#define TX  32
#define TY  8
#define KC  8
#define NCHUNK (C_ / KC)
#define NT  224          // 7 warps, warp = dj

#define S1_ROW 36                   // 144B rows: slot stride 9 (odd) -> conflict-free
#define S1_CH  (TY * S1_ROW)        // 288
#define S2_ROW 44                   // 176B rows: slot stride 11 (odd) -> conflict-free
#define S2_CH  ((TY + 6) * S2_ROW)  // 616
#define S1_SIZE (KC * S1_CH)        // 2304
#define S2_SIZE (KC * S2_CH)        // 4928
#define BUF_SIZE (S1_SIZE + S2_SIZE)               // 7232 floats
#define NBUF 3
#define BUF_BYTES (BUF_SIZE * 4)
#define SMEM_BYTES (NBUF * BUF_BYTES)              // 86784 B per CTA

typedef unsigned long long ull;

__device__ __forceinline__ uint32_t sptr(const void* p) {
    return (uint32_t)__cvta_generic_to_shared(p);
}
__device__ __forceinline__ void cp16s(uint32_t dst, const float* src, bool pred) {
    int bytes = pred ? 16 : 0;
    asm volatile("cp.async.cg.shared.global [%0], [%1], 16, %2;\n"
                 :: "r"(dst), "l"(src), "r"(bytes));
}
__device__ __forceinline__ void cp_commit() {
    asm volatile("cp.async.commit_group;\n" ::: "memory");
}
__device__ __forceinline__ void lds2(ull& a, ull& b, uint32_t addr) {
    asm volatile("ld.shared.v2.u64 {%0,%1}, [%2];"
                 : "=l"(a), "=l"(b) : "r"(addr));
}
__device__ __forceinline__ void fma2(ull& d, ull a, ull b) {
    asm("fma.rn.f32x2 %0, %1, %2, %0;" : "+l"(d) : "l"(a), "l"(b));
}
__device__ __forceinline__ void unpack2(float& lo, float& hi, ull v) {
    asm("mov.b64 {%0,%1}, %2;" : "=f"(lo), "=f"(hi) : "l"(v));
}

__device__ __forceinline__ void load_ef(
    uint32_t a1, uint32_t a2, ull (&f)[4], ull (&e)[8])
{
    lds2(f[0], f[1], a1);
    lds2(f[2], f[3], a1 + 16);
    lds2(e[0], e[1], a2);
    lds2(e[2], e[3], a2 + 16);
    lds2(e[4], e[5], a2 + 32);
    lds2(e[6], e[7], a2 + 48);
}

__device__ __forceinline__ void compute_ch(
    ull* __restrict__ acc2, const ull (&f)[4], const ull (&e)[8])
{
    ull o[7];
#pragma unroll
    for (int t = 0; t < 7; ++t)
        o[t] = (e[t] >> 32) | (e[t + 1] << 32);
#pragma unroll
    for (int d = 0; d < 7; ++d) {
#pragma unroll
        for (int pp = 0; pp < 4; ++pp) {
            ull vp = (d & 1) ? e[(d + 1) / 2 + pp] : o[d / 2 + pp];
            fma2(acc2[d * 4 + pp], f[pp], vp);
        }
    }
}

// Full burst loader (prologue only).
__device__ __forceinline__ void load_chunk_burst(
    uint32_t s1, uint32_t s2,
    const float* __restrict__ fbase, const float* __restrict__ sbase,
    int c0, int x0, int y0, int tid)
{
    const size_t HW = (size_t)H_ * W_;
#pragma unroll
    for (int it = 0; it < 3; ++it) {
        int u = tid + it * NT;
        if (it < 2 || u < 512) {
            int c = u >> 6;
            int row = (u >> 3) & 7;
            int q = u & 7;
            const float* src = fbase + (size_t)(c0 + c) * HW + (size_t)(y0 + row) * W_ + x0 + q * 4;
            cp16s(s1 + (uint32_t)(c * S1_CH + row * S1_ROW + q * 4) * 4, src, true);
        }
    }
    const int row = tid >> 4;
    const int q   = tid & 15;
    if (q < 11) {
        const int gy = y0 - 3 + row;
        const int gx = x0 - 4 + q * 4;
        const bool p = (gy >= 0) && (gy < H_) && (gx >= 0) && (gx < W_);
        const int gyc = gy < 0 ? 0 : (gy >= H_ ? H_ - 1 : gy);
        const int gxc = gx < 0 ? 0 : (gx >= W_ ? W_ - 1 : gx);
        const float* src0 = sbase + (size_t)c0 * HW + (size_t)gyc * W_ + gxc;
        uint32_t dst0 = s2 + (uint32_t)(row * S2_ROW + q * 4) * 4;
#pragma unroll
        for (int c = 0; c < KC; ++c)
            cp16s(dst0 + (uint32_t)(c * S2_CH) * 4, src0 + c * HW, p);
    }
}

struct LoaderState {
    const float* src2;
    const float* src1[3];
    uint32_t dst2;
    uint32_t dst1[3];
    bool l2act, p2;
    bool act1[3];
};

// One chunk: 8 channels, register-double-buffered; optionally interleaves
// the cp.async stream for chunk k+2 between compute slots.
template<bool DOLOAD>
__device__ __forceinline__ void chunk_body(
    ull* __restrict__ acc2, uint32_t a1, uint32_t a2,
    const LoaderState& L, uint32_t loff, uint32_t smem_base)
{
    const size_t HW = (size_t)H_ * W_;
    const uint32_t ld2 = smem_base + loff + L.dst2;

    ull f0[4], e0[8], f1[4], e1[8];
    load_ef(a1, a2, f0, e0);                     // c = 0

#pragma unroll
    for (int c = 0; c < KC; c += 2) {
        a1 += S1_CH * 4; a2 += S2_CH * 4;
        load_ef(a1, a2, f1, e1);                 // c+1
        if (DOLOAD && L.l2act)
            cp16s(ld2 + (uint32_t)(c * S2_CH) * 4, L.src2 + (size_t)c * HW, L.p2);
        if (DOLOAD && c < 6 && L.act1[c >> 1])
            cp16s(smem_base + loff + L.dst1[c >> 1], L.src1[c >> 1], true);
        compute_ch(acc2, f0, e0);                // c
        if (c + 2 < KC) {
            a1 += S1_CH * 4; a2 += S2_CH * 4;
            load_ef(a1, a2, f0, e0);             // c+2
        }
        if (DOLOAD && L.l2act)
            cp16s(ld2 + (uint32_t)((c + 1) * S2_CH) * 4, L.src2 + (size_t)(c + 1) * HW, L.p2);
        compute_ch(acc2, f1, e1);                // c+1
    }
}

__global__ void __launch_bounds__(NT, 2)
corr_kernel(const float* __restrict__ first,
            const float* __restrict__ second,
            float* __restrict__ out)
{
    extern __shared__ float smem[];
    const int tid = threadIdx.x;
    const int dj = tid >> 5;                  // warp = row displacement 0..6
    const int lane = tid & 31;
    // Conflict-free lane map: 8-lane LDS wavefront = 8 consecutive rows.
    const int tyl = lane & 7;
    const int txl = lane >> 3;
    const int xl = txl * 8;
    const int bx = blockIdx.x, by = blockIdx.y, b = blockIdx.z;
    const int x0 = bx * TX, y0 = by * TY;

    const size_t HW = (size_t)H_ * W_;
    const float* fbase = first  + (size_t)b * C_ * HW;
    const float* sbase = second + (size_t)b * C_ * HW;

    const uint32_t smem_base = sptr(smem);
    const uint32_t s1_thr = smem_base + (uint32_t)(tyl * S1_ROW + xl) * 4;
    const uint32_t s2_thr = smem_base + (uint32_t)S1_SIZE * 4
                          + (uint32_t)((tyl + dj) * S2_ROW + xl) * 4;

    // ---- persistent loader state ----
    LoaderState L;
    {
        const int l2row = tid >> 4;
        const int l2q   = tid & 15;
        L.l2act = (l2q < 11);
        int gy = y0 - 3 + l2row;
        int gx = x0 - 4 + l2q * 4;
        L.p2 = L.l2act && (gy >= 0) && (gy < H_) && (gx >= 0) && (gx < W_);
        if (gy < 0) gy = 0; if (gy >= H_) gy = H_ - 1;
        if (gx < 0) gx = 0; if (gx >= W_) gx = W_ - 1;
        L.src2 = sbase + (size_t)(2 * KC) * HW + (size_t)gy * W_ + gx;
        L.dst2 = (uint32_t)(S1_SIZE + l2row * S2_ROW + l2q * 4) * 4;
#pragma unroll
        for (int i = 0; i < 3; ++i) {
            int u = tid + i * NT;
            L.act1[i] = (u < 512);
            int c = u >> 6;
            int row = (u >> 3) & 7;
            int q = u & 7;
            L.src1[i] = fbase + (size_t)(2 * KC + c) * HW + (size_t)(y0 + row) * W_ + x0 + q * 4;
            L.dst1[i] = (uint32_t)(c * S1_CH + row * S1_ROW + q * 4) * 4;
        }
    }

    ull acc2[28];
#pragma unroll
    for (int i = 0; i < 28; ++i) acc2[i] = 0ull;

    // Prologue: burst-fill buffers 0 and 1.
    load_chunk_burst(smem_base, smem_base + (uint32_t)S1_SIZE * 4,
                     fbase, sbase, 0, x0, y0, tid);
    cp_commit();
    load_chunk_burst(smem_base + BUF_BYTES, smem_base + BUF_BYTES + (uint32_t)S1_SIZE * 4,
                     fbase, sbase, KC, x0, y0, tid);
    cp_commit();

    uint32_t coff = 0;              // compute buffer byte offset
    uint32_t loff = 2 * BUF_BYTES;  // load buffer byte offset

    // Main: chunks 0..NCHUNK-3 interleave loads for k+2.
#pragma unroll 1
    for (int k = 0; k < NCHUNK - 2; ++k) {
        asm volatile("cp.async.wait_group 1;\n" ::: "memory");
        __syncthreads();
        chunk_body<true>(acc2, s1_thr + coff, s2_thr + coff, L, loff, smem_base);
        cp_commit();
        L.src2 += KC * HW;
#pragma unroll
        for (int i = 0; i < 3; ++i) L.src1[i] += KC * HW;
        coff += BUF_BYTES; if (coff == NBUF * BUF_BYTES) coff = 0;
        loff += BUF_BYTES; if (loff == NBUF * BUF_BYTES) loff = 0;
    }
    // Tail chunk NCHUNK-2 (no loads).
    asm volatile("cp.async.wait_group 1;\n" ::: "memory");
    __syncthreads();
    chunk_body<false>(acc2, s1_thr + coff, s2_thr + coff, L, loff, smem_base);
    coff += BUF_BYTES; if (coff == NBUF * BUF_BYTES) coff = 0;
    // Tail chunk NCHUNK-1.
    asm volatile("cp.async.wait_group 0;\n" ::: "memory");
    __syncthreads();
    chunk_body<false>(acc2, s1_thr + coff, s2_thr + coff, L, loff, smem_base);

    // epilogue: mean over channels; warp dj owns flattened d = dj*7 + di
    const float invC = 1.0f / (float)C_;
    const int y = y0 + tyl;
    const int x = x0 + xl;
#pragma unroll
    for (int d = 0; d < 7; ++d) {
        float r[8];
#pragma unroll
        for (int pp = 0; pp < 4; ++pp)
            unpack2(r[pp * 2], r[pp * 2 + 1], acc2[d * 4 + pp]);
        float* op = out + (((size_t)b * ND + dj * 7 + d) * H_ + y) * W_ + x;
        float4 o0, o1;
        o0.x = r[0] * invC; o0.y = r[1] * invC;
        o0.z = r[2] * invC; o0.w = r[3] * invC;
        o1.x = r[4] * invC; o1.y = r[5] * invC;
        o1.z = r[6] * invC; o1.w = r[7] * invC;
        ((float4*)op)[0] = o0;
        ((float4*)op)[1] = o1;
    }
}

extern "C" void kernel_launch(void* const* d_in, const int* in_sizes, int n_in,
                              void* d_out, int out_size)
{
    const float* first  = (const float*)d_in[0];
    const float* second = (const float*)d_in[1];
    float* out = (float*)d_out;

    cudaFuncSetAttribute(corr_kernel,
                         cudaFuncAttributeMaxDynamicSharedMemorySize,
                         (int)SMEM_BYTES);

    dim3 grid(W_ / TX, H_ / TY, B_);   // 14 x 24 x 8 = 2688 CTAs
    dim3 block(NT);
    corr_kernel<<<grid, block, SMEM_BYTES>>>(first, second, out);
}

// round 16
// speedup vs baseline: 1.0785x; 1.0785x over previous
#include <cuda_runtime.h>
#include <cstdint>

#define B_  8
#define C_  128
#define H_  192
#define W_  448
#define ND  49

#define TX  32
#define TY  8
#define KC  8
#define NCHUNK (C_ / KC)
#define NT  224          // 7 warps, warp = dj

#define S1_ROW 36                   // 144B rows: slot stride 9 (odd) -> conflict-free
#define S1_CH  (TY * S1_ROW)        // 288
#define S2_ROW 44                   // 176B rows: slot stride 11 (odd) -> conflict-free
#define S2_CH  ((TY + 6) * S2_ROW)  // 616
#define S1_SIZE (KC * S1_CH)        // 2304
#define S2_SIZE (KC * S2_CH)        // 4928
#define BUF_SIZE (S1_SIZE + S2_SIZE)               // 7232 floats
#define NBUF 3
#define BUF_BYTES (BUF_SIZE * 4)
#define SMEM_BYTES (NBUF * BUF_BYTES)              // 86784 B per CTA

typedef unsigned long long ull;

__device__ __forceinline__ uint32_t sptr(const void* p) {
    return (uint32_t)__cvta_generic_to_shared(p);
}
__device__ __forceinline__ void cp16(void* dst, const float* src, bool pred) {
    int bytes = pred ? 16 : 0;
    asm volatile("cp.async.cg.shared.global [%0], [%1], 16, %2;\n"
                 :: "r"(sptr(dst)), "l"(src), "r"(bytes));
}
__device__ __forceinline__ void cp_commit() {
    asm volatile("cp.async.commit_group;\n" ::: "memory");
}
__device__ __forceinline__ void lds2(ull& a, ull& b, uint32_t addr) {
    asm volatile("ld.shared.v2.u64 {%0,%1}, [%2];"
                 : "=l"(a), "=l"(b) : "r"(addr));
}
__device__ __forceinline__ void fma2(ull& d, ull a, ull b) {
    asm("fma.rn.f32x2 %0, %1, %2, %0;" : "+l"(d) : "l"(a), "l"(b));
}
__device__ __forceinline__ void unpack2(float& lo, float& hi, ull v) {
    asm("mov.b64 {%0,%1}, %2;" : "=f"(lo), "=f"(hi) : "l"(v));
}
__device__ __forceinline__ void pack2(ull& o, float lo, float hi) {
    asm("mov.b64 %0, {%1,%2};" : "=l"(o) : "f"(lo), "f"(hi));
}

__device__ __forceinline__ void load_ef(
    uint32_t a1, uint32_t a2, ull (&f)[4], ull (&e)[8])
{
    lds2(f[0], f[1], a1);
    lds2(f[2], f[3], a1 + 16);
    lds2(e[0], e[1], a2);
    lds2(e[2], e[3], a2 + 16);
    lds2(e[4], e[5], a2 + 32);
    lds2(e[6], e[7], a2 + 48);
}

// Displacement-parity split compute: no o[] realignment needed.
//   odd d = 2dd+1 (dd 0..2): px even-pairs x aligned e-pairs.    accO[dd*4+pp]
//   even d = 2ed (ed 0..3): px odd-pairs (1,2)(3,4)(5,6) x aligned e-pairs,
//                           plus scalar FFMA for px 0 and px 7.  accE[ed*3+qq], accS[ed*2+{0,1}]
__device__ __forceinline__ void compute_ch(
    ull* __restrict__ accO, ull* __restrict__ accE, float* __restrict__ accS,
    const ull (&f)[4], const ull (&e)[8])
{
    float fl[8], el[16];
#pragma unroll
    for (int i = 0; i < 4; ++i) unpack2(fl[2 * i], fl[2 * i + 1], f[i]);
#pragma unroll
    for (int i = 0; i < 8; ++i) unpack2(el[2 * i], el[2 * i + 1], e[i]);

    ull fo[3];   // odd f-pairs (f1,f2) (f3,f4) (f5,f6)
#pragma unroll
    for (int q = 0; q < 3; ++q) pack2(fo[q], fl[2 * q + 1], fl[2 * q + 2]);

    // odd d: v-pair for px pair pp is e[dd+1+pp]
#pragma unroll
    for (int dd = 0; dd < 3; ++dd)
#pragma unroll
        for (int pp = 0; pp < 4; ++pp)
            fma2(accO[dd * 4 + pp], f[pp], e[dd + 1 + pp]);

    // even d
#pragma unroll
    for (int ed = 0; ed < 4; ++ed) {
#pragma unroll
        for (int qq = 0; qq < 3; ++qq)
            fma2(accE[ed * 3 + qq], fo[qq], e[ed + qq + 1]);
        accS[ed * 2 + 0] += fl[0] * el[2 * ed + 1];     // px0: v[d+1]
        accS[ed * 2 + 1] += fl[7] * el[2 * (ed + 4)];   // px7: v[d+8]
    }
}

// Full burst loader (as R13).
__device__ __forceinline__ void load_chunk(
    float* __restrict__ s1, float* __restrict__ s2,
    const float* __restrict__ fbase, const float* __restrict__ sbase,
    int c0, int x0, int y0, int tid)
{
    const size_t HW = (size_t)H_ * W_;
#pragma unroll
    for (int it = 0; it < 3; ++it) {
        int u = tid + it * NT;
        if (it < 2 || u < 512) {
            int c = u >> 6;
            int row = (u >> 3) & 7;
            int q = u & 7;
            const float* src = fbase + (size_t)(c0 + c) * HW + (size_t)(y0 + row) * W_ + x0 + q * 4;
            cp16(s1 + c * S1_CH + row * S1_ROW + q * 4, src, true);
        }
    }
    const int row = tid >> 4;
    const int q   = tid & 15;
    if (q < 11) {
        const int gy = y0 - 3 + row;
        const int gx = x0 - 4 + q * 4;
        const bool p = (gy >= 0) && (gy < H_) && (gx >= 0) && (gx < W_);
        const int gyc = gy < 0 ? 0 : (gy >= H_ ? H_ - 1 : gy);
        const int gxc = gx < 0 ? 0 : (gx >= W_ ? W_ - 1 : gx);
        const float* src0 = sbase + (size_t)c0 * HW + (size_t)gyc * W_ + gxc;
        float* dst0 = s2 + row * S2_ROW + q * 4;
#pragma unroll
        for (int c = 0; c < KC; ++c)
            cp16(dst0 + c * S2_CH, src0 + c * HW, p);
    }
}

__global__ void __launch_bounds__(NT, 2)
corr_kernel(const float* __restrict__ first,
            const float* __restrict__ second,
            float* __restrict__ out)
{
    extern __shared__ float smem[];
    const int tid = threadIdx.x;
    const int dj = tid >> 5;                  // warp = row displacement 0..6
    const int lane = tid & 31;
    // Conflict-free lane map: 8-lane LDS wavefront = 8 consecutive rows.
    const int tyl = lane & 7;
    const int txl = lane >> 3;
    const int xl = txl * 8;
    const int bx = blockIdx.x, by = blockIdx.y, b = blockIdx.z;
    const int x0 = bx * TX, y0 = by * TY;

    const size_t HW = (size_t)H_ * W_;
    const float* fbase = first  + (size_t)b * C_ * HW;
    const float* sbase = second + (size_t)b * C_ * HW;

    const uint32_t smem_base = sptr(smem);
    const uint32_t s1_thr = smem_base + (uint32_t)(tyl * S1_ROW + xl) * 4;
    const uint32_t s2_thr = smem_base + (uint32_t)S1_SIZE * 4
                          + (uint32_t)((tyl + dj) * S2_ROW + xl) * 4;

    ull accO[12];    // odd d
    ull accE[12];    // even d, px pairs (1,2)(3,4)(5,6)
    float accS[8];   // even d, px 0 and 7
#pragma unroll
    for (int i = 0; i < 12; ++i) { accO[i] = 0ull; accE[i] = 0ull; }
#pragma unroll
    for (int i = 0; i < 8; ++i) accS[i] = 0.0f;

    // 3-stage smem pipeline: prologue fills buffers 0 and 1.
    load_chunk(smem, smem + S1_SIZE, fbase, sbase, 0, x0, y0, tid);
    cp_commit();
    load_chunk(smem + BUF_SIZE, smem + BUF_SIZE + S1_SIZE, fbase, sbase, KC, x0, y0, tid);
    cp_commit();

    uint32_t coff = 0;
    int lidx = 2;

#pragma unroll 1
    for (int k = 0; k < NCHUNK; ++k) {
        if (k < NCHUNK - 1) {
            asm volatile("cp.async.wait_group 1;\n" ::: "memory");
        } else {
            asm volatile("cp.async.wait_group 0;\n" ::: "memory");
        }
        __syncthreads();   // buffer lidx free, buffer k visible

        if (k + 2 < NCHUNK) {
            float* nb = smem + lidx * BUF_SIZE;
            load_chunk(nb, nb + S1_SIZE, fbase, sbase, (k + 2) * KC, x0, y0, tid);
            cp_commit();
        }

        uint32_t a1 = s1_thr + coff;
        uint32_t a2 = s2_thr + coff;

        // Register double-buffered channel pipeline.
        ull f0[4], e0[8], f1[4], e1[8];
        load_ef(a1, a2, f0, e0);
#pragma unroll
        for (int c = 0; c < KC; c += 2) {
            a1 += S1_CH * 4; a2 += S2_CH * 4;
            load_ef(a1, a2, f1, e1);
            compute_ch(accO, accE, accS, f0, e0);
            if (c + 2 < KC) {
                a1 += S1_CH * 4; a2 += S2_CH * 4;
                load_ef(a1, a2, f0, e0);
            }
            compute_ch(accO, accE, accS, f1, e1);
        }

        coff += BUF_BYTES;
        if (coff == NBUF * BUF_BYTES) coff = 0;
        if (++lidx == NBUF) lidx = 0;
    }

    // epilogue: mean over channels; warp dj owns flattened d = dj*7 + d
    const float invC = 1.0f / (float)C_;
    const int y = y0 + tyl;
    const int x = x0 + xl;
#pragma unroll
    for (int d = 0; d < 7; ++d) {
        float r[8];
        if (d & 1) {
            const int dd = (d - 1) / 2;
#pragma unroll
            for (int pp = 0; pp < 4; ++pp)
                unpack2(r[pp * 2], r[pp * 2 + 1], accO[dd * 4 + pp]);
        } else {
            const int ed = d / 2;
            r[0] = accS[ed * 2 + 0];
#pragma unroll
            for (int qq = 0; qq < 3; ++qq)
                unpack2(r[2 * qq + 1], r[2 * qq + 2], accE[ed * 3 + qq]);
            r[7] = accS[ed * 2 + 1];
        }
        float* op = out + (((size_t)b * ND + dj * 7 + d) * H_ + y) * W_ + x;
        float4 o0, o1;
        o0.x = r[0] * invC; o0.y = r[1] * invC;
        o0.z = r[2] * invC; o0.w = r[3] * invC;
        o1.x = r[4] * invC; o1.y = r[5] * invC;
        o1.z = r[6] * invC; o1.w = r[7] * invC;
        ((float4*)op)[0] = o0;
        ((float4*)op)[1] = o1;
    }
}

extern "C" void kernel_launch(void* const* d_in, const int* in_sizes, int n_in,
                              void* d_out, int out_size)
{
    const float* first  = (const float*)d_in[0];
    const float* second = (const float*)d_in[1];
    float* out = (float*)d_out;

    cudaFuncSetAttribute(corr_kernel,
                         cudaFuncAttributeMaxDynamicSharedMemorySize,
                         (int)SMEM_BYTES);

    dim3 grid(W_ / TX, H_ / TY, B_);   // 14 x 24 x 8 = 2688 CTAs
    dim3 block(NT);
    corr_kernel<<<grid, block, SMEM_BYTES>>>(first, second, out);
}